// round 12
// baseline (speedup 1.0000x reference)
#include <cuda_runtime.h>
#include <cuda_fp16.h>
#include <cstdint>

#define B_DIM   256
#define D_DIM   512
#define OUT_DIM 1024
#define H_DIM   131328          // (D+1)*D/2
#define SPLITS  18
#define TPS     114             // k-tiles per split (H/64/18, exact)
#define KT      64
#define NTHREADS 256
#define STAGE_W_OFF 32768       // A: 256x64 fp16 = 32KB, W: 128x64 fp16 = 16KB
#define STAGE_SZ    49152
#define SMEM_TOTAL  (2*STAGE_SZ)   // 96KB

__device__ __half g_A[(size_t)B_DIM * H_DIM];    // packed x_i*x_j, fp16

// ---------------- prep: A[m][h] = fp16(x[m,i]*x[m,j]), pairs inline ----------------
__global__ void prep_A_kernel(const float* __restrict__ x) {
    int m    = blockIdx.y * 8 + (threadIdx.x >> 5);
    int lane = threadIdx.x & 31;
    int h0   = blockIdx.x * 256 + lane * 8;          // grid.x=513 -> full H exactly
    const float* xr = x + m * D_DIM;

    float s = sqrtf((float)(1050625 - 8 * h0));      // (2D+1)^2 - 8h
    int i = (int)((1025.0f - s) * 0.5f);
    i = min(max(i, 0), 511);
    while (i > 0 && (i * (1025 - i)) / 2 > h0) --i;
    while ((((i + 1) * (1024 - i)) / 2) <= h0) ++i;
    int rem = h0 - (i * (1025 - i)) / 2;             // j = i + rem

    float xi = __ldg(xr + i);
    __half hv[8];
    #pragma unroll
    for (int u = 0; u < 8; ++u) {
        hv[u] = __float2half_rn(xi * __ldg(xr + i + rem));
        ++rem;
        if (i + rem > 511) { ++i; rem = 0; xi = __ldg(xr + i); }
    }
    *(uint4*)(&g_A[(size_t)m * H_DIM + h0]) = *(uint4*)hv;
}

// ---------------- main GEMM: C = A(256xH) * W^T(Hx1024) ----------------
// fp16 HMMA with fp16 accumulators, folded to fp32 once per 64-k tile chain.
__global__ void __launch_bounds__(NTHREADS, 1) qgemm_kernel(const float* __restrict__ W,
                                                            float* __restrict__ out) {
    extern __shared__ char smem[];
    const uint32_t sb = (uint32_t)__cvta_generic_to_shared(smem);
    const int tid  = threadIdx.x;
    const int bx   = blockIdx.x;                     // 144 CTAs
    const int ng   = bx & 7, split = bx >> 3;
    const int n0   = ng * 128;
    const int lane = tid & 31, warp = tid >> 5;      // 8 warps
    const int wm   = warp >> 1, wn = warp & 1;       // (4 m x 2 n), warp tile 64x64
    const int kt0  = split * TPS;
    const float4* Wv = (const float4*)W;

    float acc[4][8][4];
    #pragma unroll
    for (int a = 0; a < 4; ++a)
        #pragma unroll
        for (int b = 0; b < 8; ++b)
            #pragma unroll
            for (int e = 0; e < 4; ++e) acc[a][b][e] = 0.f;

    const int lrow = lane & 15;
    const int lcol = (lane >> 4) * 16;
    const uint32_t lxor = (uint32_t)((lrow & 7) << 4);

    // ---- prologue: fill stage 0 ----
    {
        const int k0 = kt0 * KT;
        #pragma unroll
        for (int c = 0; c < 8; ++c) {                // A: 256 rows x 128B via cp.async
            int flat = tid + c * NTHREADS, row = flat >> 3, ch = flat & 7;
            uint32_t dst = sb + row * 128 + (((uint32_t)(ch * 16)) ^ ((uint32_t)((row & 7) << 4)));
            const __half* src = &g_A[(size_t)row * H_DIM + k0 + ch * 8];
            asm volatile("cp.async.cg.shared.global [%0], [%1], 16;" :: "r"(dst), "l"(src) : "memory");
        }
        asm volatile("cp.async.commit_group;" ::: "memory");
        #pragma unroll
        for (int it = 0; it < 8; ++it) {             // W: 128 rows x 64 fp32 -> fp16
            int f = tid + it * NTHREADS, n = f >> 4, q = f & 15;
            float4 w = __ldcs(&Wv[(size_t)(n0 + n) * (H_DIM / 4) + (k0 >> 2) + q]);
            __half2 h01 = __floats2half2_rn(w.x, w.y);
            __half2 h23 = __floats2half2_rn(w.z, w.w);
            uint32_t off = sb + STAGE_W_OFF + n * 128 +
                           (((uint32_t)(q * 8)) ^ ((uint32_t)((n & 7) << 4)));
            asm volatile("st.shared.v2.b32 [%0], {%1,%2};"
                         :: "r"(off), "r"(*(const uint32_t*)&h01), "r"(*(const uint32_t*)&h23)
                         : "memory");
        }
        asm volatile("cp.async.wait_group 0;" ::: "memory");
        __syncthreads();
    }

    for (int t = 0; t < TPS; ++t) {
        const int p = t & 1;
        float4 wv[8];
        if (t < TPS - 1) {                           // issue next-stage loads (R8 burst style)
            const int k1 = (kt0 + t + 1) * KT;
            const uint32_t fb = sb + (p ^ 1) * STAGE_SZ;
            #pragma unroll
            for (int c = 0; c < 8; ++c) {
                int flat = tid + c * NTHREADS, row = flat >> 3, ch = flat & 7;
                uint32_t dst = fb + row * 128 + (((uint32_t)(ch * 16)) ^ ((uint32_t)((row & 7) << 4)));
                const __half* src = &g_A[(size_t)row * H_DIM + k1 + ch * 8];
                asm volatile("cp.async.cg.shared.global [%0], [%1], 16;" :: "r"(dst), "l"(src) : "memory");
            }
            asm volatile("cp.async.commit_group;" ::: "memory");
            #pragma unroll
            for (int it = 0; it < 8; ++it) {
                int f = tid + it * NTHREADS, n = f >> 4, q = f & 15;
                wv[it] = __ldcs(&Wv[(size_t)(n0 + n) * (H_DIM / 4) + (k1 >> 2) + q]);
            }
        }

        // ---- compute current stage: mi-pair outer, fp16 accum chains of 4 HMMA ----
        const uint32_t Ab = sb + p * STAGE_SZ;
        const uint32_t Wb = Ab + STAGE_W_OFF;
        #pragma unroll
        for (int mip = 0; mip < 2; ++mip) {
            uint32_t hacc[2][8][2];
            #pragma unroll
            for (int mi2 = 0; mi2 < 2; ++mi2)
                #pragma unroll
                for (int ni = 0; ni < 8; ++ni) { hacc[mi2][ni][0] = 0u; hacc[mi2][ni][1] = 0u; }

            #pragma unroll
            for (int ks = 0; ks < 4; ++ks) {
                uint32_t a[2][4];
                #pragma unroll
                for (int mi2 = 0; mi2 < 2; ++mi2) {
                    int row = wm * 64 + (mip * 2 + mi2) * 16 + lrow;
                    uint32_t ad = Ab + row * 128 + (((uint32_t)(ks * 32 + lcol)) ^ lxor);
                    asm volatile("ldmatrix.sync.aligned.m8n8.x4.shared.b16 {%0,%1,%2,%3}, [%4];"
                                 : "=r"(a[mi2][0]), "=r"(a[mi2][1]), "=r"(a[mi2][2]), "=r"(a[mi2][3])
                                 : "r"(ad));
                }
                uint32_t bfr[8][2];
                #pragma unroll
                for (int nj = 0; nj < 4; ++nj) {
                    int row = wn * 64 + nj * 16 + lrow;
                    uint32_t bd = Wb + row * 128 + (((uint32_t)(ks * 32 + lcol)) ^ lxor);
                    uint32_t r0, r1, r2, r3;
                    asm volatile("ldmatrix.sync.aligned.m8n8.x4.shared.b16 {%0,%1,%2,%3}, [%4];"
                                 : "=r"(r0), "=r"(r1), "=r"(r2), "=r"(r3) : "r"(bd));
                    bfr[nj * 2][0] = r0;     bfr[nj * 2][1] = r2;
                    bfr[nj * 2 + 1][0] = r1; bfr[nj * 2 + 1][1] = r3;
                }
                #pragma unroll
                for (int mi2 = 0; mi2 < 2; ++mi2)
                    #pragma unroll
                    for (int ni = 0; ni < 8; ++ni)
                        asm volatile("mma.sync.aligned.m16n8k16.row.col.f16.f16.f16.f16 "
                                     "{%0,%1}, {%2,%3,%4,%5}, {%6,%7}, {%0,%1};"
                                     : "+r"(hacc[mi2][ni][0]), "+r"(hacc[mi2][ni][1])
                                     : "r"(a[mi2][0]), "r"(a[mi2][1]), "r"(a[mi2][2]), "r"(a[mi2][3]),
                                       "r"(bfr[ni][0]), "r"(bfr[ni][1]));
            }
            // fold fp16 chains into fp32 accumulators
            #pragma unroll
            for (int mi2 = 0; mi2 < 2; ++mi2)
                #pragma unroll
                for (int ni = 0; ni < 8; ++ni) {
                    float2 f0 = __half22float2(*reinterpret_cast<__half2*>(&hacc[mi2][ni][0]));
                    float2 f1 = __half22float2(*reinterpret_cast<__half2*>(&hacc[mi2][ni][1]));
                    acc[mip * 2 + mi2][ni][0] += f0.x;
                    acc[mip * 2 + mi2][ni][1] += f0.y;
                    acc[mip * 2 + mi2][ni][2] += f1.x;
                    acc[mip * 2 + mi2][ni][3] += f1.y;
                }
        }

        if (t < TPS - 1) {                           // convert + store W, drain A cp.async
            const uint32_t fw = sb + (p ^ 1) * STAGE_SZ + STAGE_W_OFF;
            #pragma unroll
            for (int it = 0; it < 8; ++it) {
                int f = tid + it * NTHREADS, n = f >> 4, q = f & 15;
                __half2 h01 = __floats2half2_rn(wv[it].x, wv[it].y);
                __half2 h23 = __floats2half2_rn(wv[it].z, wv[it].w);
                uint32_t off = fw + n * 128 + (((uint32_t)(q * 8)) ^ ((uint32_t)((n & 7) << 4)));
                asm volatile("st.shared.v2.b32 [%0], {%1,%2};"
                             :: "r"(off), "r"(*(const uint32_t*)&h01), "r"(*(const uint32_t*)&h23)
                             : "memory");
            }
            asm volatile("cp.async.wait_group 0;" ::: "memory");
        }
        __syncthreads();
    }

    // ---- epilogue: accumulate split partial directly into out ----
    #pragma unroll
    for (int mi = 0; mi < 4; ++mi)
        #pragma unroll
        for (int ni = 0; ni < 8; ++ni)
            #pragma unroll
            for (int e = 0; e < 4; ++e) {
                int m = wm * 64 + mi * 16 + (lane >> 2) + 8 * (e >> 1);
                int n = n0 + wn * 64 + ni * 8 + (lane & 3) * 2 + (e & 1);
                atomicAdd(&out[(size_t)m * OUT_DIM + n], acc[mi][ni][e]);
            }
}

extern "C" void kernel_launch(void* const* d_in, const int* in_sizes, int n_in,
                              void* d_out, int out_size) {
    const float* x = (const float*)d_in[0];
    const float* W = (const float*)d_in[1];
    if (in_sizes[0] != B_DIM * D_DIM) { x = (const float*)d_in[1]; W = (const float*)d_in[0]; }
    cudaFuncSetAttribute(qgemm_kernel, cudaFuncAttributeMaxDynamicSharedMemorySize, SMEM_TOTAL);
    cudaMemsetAsync(d_out, 0, (size_t)out_size * sizeof(float));
    prep_A_kernel<<<dim3(513, 32), 256>>>(x);
    qgemm_kernel<<<144, NTHREADS, SMEM_TOTAL>>>(W, (float*)d_out);
}

// round 13
// speedup vs baseline: 1.2184x; 1.2184x over previous
#include <cuda_runtime.h>
#include <cuda_fp16.h>
#include <cstdint>

#define B_DIM   256
#define D_DIM   512
#define OUT_DIM 1024
#define H_DIM   131328          // (D+1)*D/2
#define SPLITS  18
#define TPS     114             // k-tiles per split (H/64/18, exact); even -> 57 periods
#define KT      64
#define NTHREADS 512

// 4-stage buffers: A[s] 256x64 fp16 = 32KB, W[s] 128x64 fp16 = 16KB
#define A_STAGE  32768
#define W_BASE   131072
#define W_STAGE  16384
#define SMEM_TOTAL 196608       // 4*(32K+16K) = 192KB

__device__ __half g_A[(size_t)B_DIM * H_DIM];    // packed x_i*x_j, fp16

// ---------------- prep: A[m][h] = fp16(x[m,i]*x[m,j]), pairs inline ----------------
__global__ void __launch_bounds__(1024) prep_A_kernel(const float* __restrict__ x) {
    int m    = blockIdx.y * 32 + (threadIdx.x >> 5);
    int lane = threadIdx.x & 31;
    int h0   = blockIdx.x * 256 + lane * 8;          // grid.x=513 -> full H exactly
    const float* xr = x + m * D_DIM;

    float s = sqrtf((float)(1050625 - 8 * h0));      // (2D+1)^2 - 8h
    int i = (int)((1025.0f - s) * 0.5f);
    i = min(max(i, 0), 511);
    while (i > 0 && (i * (1025 - i)) / 2 > h0) --i;
    while ((((i + 1) * (1024 - i)) / 2) <= h0) ++i;
    int rem = h0 - (i * (1025 - i)) / 2;             // j = i + rem

    float xi = __ldg(xr + i);
    __half hv[8];
    #pragma unroll
    for (int u = 0; u < 8; ++u) {
        hv[u] = __float2half_rn(xi * __ldg(xr + i + rem));
        ++rem;
        if (i + rem > 511) { ++i; rem = 0; xi = __ldg(xr + i); }
    }
    *(uint4*)(&g_A[(size_t)m * H_DIM + h0]) = *(uint4*)hv;
}

// ---------------- main GEMM: C = A(256xH) * W^T(Hx1024), fp16 HMMA, 4-stage ----------------
__global__ void __launch_bounds__(NTHREADS, 1) qgemm_kernel(const float* __restrict__ W,
                                                            float* __restrict__ out) {
    extern __shared__ char smem[];
    const uint32_t sb = (uint32_t)__cvta_generic_to_shared(smem);
    const int tid  = threadIdx.x;
    const int bx   = blockIdx.x;                     // 144 CTAs
    const int ng   = bx & 7, split = bx >> 3;
    const int n0   = ng * 128;
    const int lane = tid & 31, warp = tid >> 5;      // 16 warps
    const int wm   = warp & 3, wn = warp >> 2;       // (4 m x 4 n), warp tile 64x32
    const int kt0  = split * TPS;
    const float4* Wv = (const float4*)W;

    float acc[4][4][4];
    #pragma unroll
    for (int a = 0; a < 4; ++a)
        #pragma unroll
        for (int b = 0; b < 4; ++b)
            #pragma unroll
            for (int e = 0; e < 4; ++e) acc[a][b][e] = 0.f;

    const int lrow = lane & 15;
    const int lcol = (lane >> 4) * 16;
    const uint32_t lxor = (uint32_t)((lrow & 7) << 4);

    // A loader: 4 cp.async x 16B per thread into stage s
    auto issueA = [&](int kt, int s) {
        const uint32_t base = sb + (uint32_t)s * A_STAGE;
        const int k = kt * KT;
        #pragma unroll
        for (int c = 0; c < 4; ++c) {
            int flat = tid + c * NTHREADS, row = flat >> 3, ch = flat & 7;
            uint32_t dst = base + row * 128 +
                           (((uint32_t)(ch * 16)) ^ ((uint32_t)((row & 7) << 4)));
            const __half* src = &g_A[(size_t)row * H_DIM + k + ch * 8];
            asm volatile("cp.async.cg.shared.global [%0], [%1], 16;" :: "r"(dst), "l"(src) : "memory");
        }
    };
    // W LDG burst: 4 float4 per thread
    auto ldgW = [&](int kt, float4* wv) {
        const int k = kt * KT;
        #pragma unroll
        for (int it = 0; it < 4; ++it) {
            int f = tid + it * NTHREADS, n = f >> 4, q = f & 15;
            wv[it] = __ldcs(&Wv[(size_t)(n0 + n) * (H_DIM / 4) + (k >> 2) + q]);
        }
    };
    // convert + store W regs into stage s
    auto cvtW = [&](const float4* wv, int s) {
        const uint32_t base = sb + W_BASE + (uint32_t)s * W_STAGE;
        #pragma unroll
        for (int it = 0; it < 4; ++it) {
            int f = tid + it * NTHREADS, n = f >> 4, q = f & 15;
            __half2 h01 = __floats2half2_rn(wv[it].x, wv[it].y);
            __half2 h23 = __floats2half2_rn(wv[it].z, wv[it].w);
            uint32_t off = base + n * 128 +
                           (((uint32_t)(q * 8)) ^ ((uint32_t)((n & 7) << 4)));
            asm volatile("st.shared.v2.b32 [%0], {%1,%2};"
                         :: "r"(off), "r"(*(const uint32_t*)&h01), "r"(*(const uint32_t*)&h23)
                         : "memory");
        }
    };
    // compute one k-tile from stage s
    auto compute = [&](int s) {
        const uint32_t Ab = sb + (uint32_t)s * A_STAGE;
        const uint32_t Wb = sb + W_BASE + (uint32_t)s * W_STAGE;
        #pragma unroll
        for (int ks = 0; ks < 4; ++ks) {
            uint32_t a[4][4];
            #pragma unroll
            for (int mi = 0; mi < 4; ++mi) {
                int row = wm * 64 + mi * 16 + lrow;
                uint32_t ad = Ab + row * 128 + (((uint32_t)(ks * 32 + lcol)) ^ lxor);
                asm volatile("ldmatrix.sync.aligned.m8n8.x4.shared.b16 {%0,%1,%2,%3}, [%4];"
                             : "=r"(a[mi][0]), "=r"(a[mi][1]), "=r"(a[mi][2]), "=r"(a[mi][3])
                             : "r"(ad));
            }
            uint32_t bfr[4][2];
            #pragma unroll
            for (int nj = 0; nj < 2; ++nj) {
                int row = wn * 32 + nj * 16 + lrow;
                uint32_t bd = Wb + row * 128 + (((uint32_t)(ks * 32 + lcol)) ^ lxor);
                uint32_t r0, r1, r2, r3;
                asm volatile("ldmatrix.sync.aligned.m8n8.x4.shared.b16 {%0,%1,%2,%3}, [%4];"
                             : "=r"(r0), "=r"(r1), "=r"(r2), "=r"(r3) : "r"(bd));
                bfr[nj * 2][0] = r0;     bfr[nj * 2][1] = r2;
                bfr[nj * 2 + 1][0] = r1; bfr[nj * 2 + 1][1] = r3;
            }
            #pragma unroll
            for (int mi = 0; mi < 4; ++mi)
                #pragma unroll
                for (int ni = 0; ni < 4; ++ni)
                    asm volatile("mma.sync.aligned.m16n8k16.row.col.f32.f16.f16.f32 "
                                 "{%0,%1,%2,%3}, {%4,%5,%6,%7}, {%8,%9}, {%0,%1,%2,%3};"
                                 : "+f"(acc[mi][ni][0]), "+f"(acc[mi][ni][1]),
                                   "+f"(acc[mi][ni][2]), "+f"(acc[mi][ni][3])
                                 : "r"(a[mi][0]), "r"(a[mi][1]), "r"(a[mi][2]), "r"(a[mi][3]),
                                   "r"(bfr[ni][0]), "r"(bfr[ni][1]));
        }
    };

    // ---- prologue: fill stages 0,1 ----
    {
        issueA(kt0 + 0, 0);
        issueA(kt0 + 1, 1);
        asm volatile("cp.async.commit_group;" ::: "memory");
        float4 wv[4];
        ldgW(kt0 + 0, wv); cvtW(wv, 0);
        ldgW(kt0 + 1, wv); cvtW(wv, 1);
        asm volatile("cp.async.wait_group 0;" ::: "memory");
        __syncthreads();
    }

    // ---- main: 57 periods of 2 tiles, one barrier per period ----
    for (int per = 0; per < TPS / 2; ++per) {
        const int tt = 2 * per;
        const bool pf = (tt + 2 < TPS);
        float4 wv[4];
        if (pf) {
            issueA(kt0 + tt + 2, (tt + 2) & 3);
            issueA(kt0 + tt + 3, (tt + 3) & 3);
            asm volatile("cp.async.commit_group;" ::: "memory");
            ldgW(kt0 + tt + 2, wv);
        }
        compute(tt & 3);
        if (pf) {
            cvtW(wv, (tt + 2) & 3);
            ldgW(kt0 + tt + 3, wv);
        }
        compute((tt + 1) & 3);
        if (pf) cvtW(wv, (tt + 3) & 3);
        asm volatile("cp.async.wait_group 0;" ::: "memory");
        __syncthreads();
    }

    // ---- epilogue: accumulate split partial directly into out ----
    #pragma unroll
    for (int mi = 0; mi < 4; ++mi)
        #pragma unroll
        for (int ni = 0; ni < 4; ++ni)
            #pragma unroll
            for (int e = 0; e < 4; ++e) {
                int m = wm * 64 + mi * 16 + (lane >> 2) + 8 * (e >> 1);
                int n = n0 + wn * 32 + ni * 8 + (lane & 3) * 2 + (e & 1);
                atomicAdd(&out[(size_t)m * OUT_DIM + n], acc[mi][ni][e]);
            }
}

extern "C" void kernel_launch(void* const* d_in, const int* in_sizes, int n_in,
                              void* d_out, int out_size) {
    const float* x = (const float*)d_in[0];
    const float* W = (const float*)d_in[1];
    if (in_sizes[0] != B_DIM * D_DIM) { x = (const float*)d_in[1]; W = (const float*)d_in[0]; }
    cudaFuncSetAttribute(qgemm_kernel, cudaFuncAttributeMaxDynamicSharedMemorySize, SMEM_TOTAL);
    cudaMemsetAsync(d_out, 0, (size_t)out_size * sizeof(float));
    prep_A_kernel<<<dim3(513, 8), 1024>>>(x);
    qgemm_kernel<<<144, NTHREADS, SMEM_TOTAL>>>(W, (float*)d_out);
}